// round 3
// baseline (speedup 1.0000x reference)
#include <cuda_runtime.h>
#include <cstdint>

// One warp per edge: 32 lanes x float4 = 128 floats per row.
// Computes out[e] = dot(srcTab[si[e]], dstTab[di[e]]) for D=128.
// Indices are int32 (JAX default x64-disabled: "int64" arrays are int32).
__global__ __launch_bounds__(256) void edge_dot128_kernel(
    const float* __restrict__ srcTab,
    const int* __restrict__ si,
    const float* __restrict__ dstTab,
    const int* __restrict__ di,
    float* __restrict__ out,
    int E)
{
    const int warp_in_block = threadIdx.x >> 5;
    const int lane = threadIdx.x & 31;
    const int e = blockIdx.x * (blockDim.x >> 5) + warp_in_block;
    if (e >= E) return;

    // All lanes load the same index words — L1 broadcast, cheap.
    const int s_idx = __ldg(&si[e]);
    const int d_idx = __ldg(&di[e]);

    const float4* __restrict__ srow =
        reinterpret_cast<const float4*>(srcTab + (size_t)s_idx * 128);
    const float4* __restrict__ drow =
        reinterpret_cast<const float4*>(dstTab + (size_t)d_idx * 128);

    // One float4 per lane from each row: fully coalesced 512B per row.
    float4 a = __ldg(&srow[lane]);
    float4 b = __ldg(&drow[lane]);

    float sum = a.x * b.x + a.y * b.y + a.z * b.z + a.w * b.w;

    // Warp tree reduction
    #pragma unroll
    for (int off = 16; off > 0; off >>= 1)
        sum += __shfl_xor_sync(0xFFFFFFFFu, sum, off);

    if (lane == 0) out[e] = sum;
}

extern "C" void kernel_launch(void* const* d_in, const int* in_sizes, int n_in,
                              void* d_out, int out_size)
{
    const float* h_user = (const float*)d_in[0];
    const float* h_item = (const float*)d_in[1];
    const int* src_clicks    = (const int*)d_in[2];
    const int* dst_clicks    = (const int*)d_in[3];
    const int* src_clickedby = (const int*)d_in[4];
    const int* dst_clickedby = (const int*)d_in[5];
    const int* src_follows   = (const int*)d_in[6];
    const int* dst_follows   = (const int*)d_in[7];
    float* out = (float*)d_out;

    const int E = in_sizes[2];  // edges per etype (500000)

    const int threads = 256;               // 8 warps = 8 edges per block
    const int edges_per_block = threads / 32;
    const int blocks = (E + edges_per_block - 1) / edges_per_block;

    // etype 0: user -> item (clicks)
    edge_dot128_kernel<<<blocks, threads>>>(
        h_user, src_clicks, h_item, dst_clicks, out, E);
    // etype 1: item -> user (clickedby)
    edge_dot128_kernel<<<blocks, threads>>>(
        h_item, src_clickedby, h_user, dst_clickedby, out + (size_t)E, E);
    // etype 2: user -> user (follows)
    edge_dot128_kernel<<<blocks, threads>>>(
        h_user, src_follows, h_user, dst_follows, out + 2 * (size_t)E, E);
}

// round 4
// speedup vs baseline: 2.1437x; 2.1437x over previous
#include <cuda_runtime.h>
#include <cstdint>

// 8 lanes per edge, 4 edges per warp. Each lane loads 4 float4 from each row
// (positions sub, sub+8, sub+16, sub+24) -> 8 independent LDG.128 (MLP=8).
// Reduction: 3 shfl_xor steps within the 8-lane group.
// All 3 etypes fused into one launch; E % 32 == 0 so each 32-edge block is a
// single etype.
__global__ __launch_bounds__(256) void edge_dot128_fused_kernel(
    const float* __restrict__ h_user,
    const float* __restrict__ h_item,
    const int* __restrict__ src_clicks,
    const int* __restrict__ dst_clicks,
    const int* __restrict__ src_clickedby,
    const int* __restrict__ dst_clickedby,
    const int* __restrict__ src_follows,
    const int* __restrict__ dst_follows,
    float* __restrict__ out,
    int E)
{
    const int lane = threadIdx.x & 31;
    const int warp_in_block = threadIdx.x >> 5;
    const int sub = lane & 7;         // position within the 8-lane group
    const int group = lane >> 3;      // which of 4 edges this warp handles

    // 32 edges per block (8 warps x 4 edges)
    const int e = blockIdx.x * 32 + warp_in_block * 4 + group;
    const int total = 3 * E;
    if (e >= total) return;

    // etype decode (block-uniform since E % 32 == 0)
    const float* srcTab;
    const float* dstTab;
    const int* si;
    const int* di;
    int el;
    if (e < E)            { srcTab = h_user; dstTab = h_item; si = src_clicks;    di = dst_clicks;    el = e; }
    else if (e < 2 * E)   { srcTab = h_item; dstTab = h_user; si = src_clickedby; di = dst_clickedby; el = e - E; }
    else                  { srcTab = h_user; dstTab = h_user; si = src_follows;   di = dst_follows;   el = e - 2 * E; }

    const int s_idx = __ldg(&si[el]);
    const int d_idx = __ldg(&di[el]);

    const float4* __restrict__ srow =
        reinterpret_cast<const float4*>(srcTab + (size_t)s_idx * 128);
    const float4* __restrict__ drow =
        reinterpret_cast<const float4*>(dstTab + (size_t)d_idx * 128);

    // 8 independent 16B loads per thread -> high MLP
    float4 a0 = __ldg(&srow[sub]);
    float4 a1 = __ldg(&srow[sub + 8]);
    float4 a2 = __ldg(&srow[sub + 16]);
    float4 a3 = __ldg(&srow[sub + 24]);
    float4 b0 = __ldg(&drow[sub]);
    float4 b1 = __ldg(&drow[sub + 8]);
    float4 b2 = __ldg(&drow[sub + 16]);
    float4 b3 = __ldg(&drow[sub + 24]);

    float sum = a0.x * b0.x + a0.y * b0.y + a0.z * b0.z + a0.w * b0.w;
    sum += a1.x * b1.x + a1.y * b1.y + a1.z * b1.z + a1.w * b1.w;
    sum += a2.x * b2.x + a2.y * b2.y + a2.z * b2.z + a2.w * b2.w;
    sum += a3.x * b3.x + a3.y * b3.y + a3.z * b3.z + a3.w * b3.w;

    // Reduce across the 8-lane group (xor masks stay within the group)
    sum += __shfl_xor_sync(0xFFFFFFFFu, sum, 1);
    sum += __shfl_xor_sync(0xFFFFFFFFu, sum, 2);
    sum += __shfl_xor_sync(0xFFFFFFFFu, sum, 4);

    if (sub == 0) out[e] = sum;
}

extern "C" void kernel_launch(void* const* d_in, const int* in_sizes, int n_in,
                              void* d_out, int out_size)
{
    const float* h_user = (const float*)d_in[0];
    const float* h_item = (const float*)d_in[1];
    const int* src_clicks    = (const int*)d_in[2];
    const int* dst_clicks    = (const int*)d_in[3];
    const int* src_clickedby = (const int*)d_in[4];
    const int* dst_clickedby = (const int*)d_in[5];
    const int* src_follows   = (const int*)d_in[6];
    const int* dst_follows   = (const int*)d_in[7];
    float* out = (float*)d_out;

    const int E = in_sizes[2];  // edges per etype (500000)
    const int total = 3 * E;

    const int threads = 256;            // 8 warps x 4 edges = 32 edges/block
    const int blocks = (total + 31) / 32;

    edge_dot128_fused_kernel<<<blocks, threads>>>(
        h_user, h_item,
        src_clicks, dst_clicks,
        src_clickedby, dst_clickedby,
        src_follows, dst_follows,
        out, E);
}

// round 6
// speedup vs baseline: 2.2157x; 1.0336x over previous
#include <cuda_runtime.h>
#include <cstdint>

// 256-bit gather with L2 evict_last (sm_103a requires v8.b32 for this policy).
// Keeps the 102MB embedding tables resident in the 126MB L2 across graph
// replays; idx/out use streaming (.cs) so they don't evict table lines.
__device__ __forceinline__ void ldg256_evict_last(const float* p, float* d)
{
    unsigned r0, r1, r2, r3, r4, r5, r6, r7;
    asm("ld.global.nc.L2::evict_last.v8.b32 {%0,%1,%2,%3,%4,%5,%6,%7}, [%8];"
        : "=r"(r0), "=r"(r1), "=r"(r2), "=r"(r3),
          "=r"(r4), "=r"(r5), "=r"(r6), "=r"(r7)
        : "l"(p));
    d[0] = __uint_as_float(r0); d[1] = __uint_as_float(r1);
    d[2] = __uint_as_float(r2); d[3] = __uint_as_float(r3);
    d[4] = __uint_as_float(r4); d[5] = __uint_as_float(r5);
    d[6] = __uint_as_float(r6); d[7] = __uint_as_float(r7);
}

// 4 lanes per edge, 8 edges per warp. Each lane loads 4 x 32B from each row
// (chunk sub, sub+4, sub+8, sub+12 of 16 x 32B chunks) -> 8 independent
// LDG.256 per thread (MLP=8). Reduction: 2 shfl_xor within the 4-lane group.
// All 3 etypes fused into one launch; etype decoded per-edge.
__global__ __launch_bounds__(256) void edge_dot128_fused_kernel(
    const float* __restrict__ h_user,
    const float* __restrict__ h_item,
    const int* __restrict__ src_clicks,
    const int* __restrict__ dst_clicks,
    const int* __restrict__ src_clickedby,
    const int* __restrict__ dst_clickedby,
    const int* __restrict__ src_follows,
    const int* __restrict__ dst_follows,
    float* __restrict__ out,
    int E)
{
    const int lane = threadIdx.x & 31;
    const int warp_in_block = threadIdx.x >> 5;
    const int sub = lane & 3;        // position within the 4-lane group
    const int group = lane >> 2;     // which of 8 edges this warp handles

    // 64 edges per block (8 warps x 8 edges)
    const int e = blockIdx.x * 64 + warp_in_block * 8 + group;
    const int total = 3 * E;
    if (e >= total) return;

    const float* srcTab;
    const float* dstTab;
    const int* si;
    const int* di;
    int el;
    if (e < E)            { srcTab = h_user; dstTab = h_item; si = src_clicks;    di = dst_clicks;    el = e; }
    else if (e < 2 * E)   { srcTab = h_item; dstTab = h_user; si = src_clickedby; di = dst_clickedby; el = e - E; }
    else                  { srcTab = h_user; dstTab = h_user; si = src_follows;   di = dst_follows;   el = e - 2 * E; }

    // Streaming index loads: read once, evict-first.
    const int s_idx = __ldcs(&si[el]);
    const int d_idx = __ldcs(&di[el]);

    const float* srow = srcTab + (size_t)s_idx * 128;
    const float* drow = dstTab + (size_t)d_idx * 128;

    // 8 independent 32B loads per thread; rows are 512B = 16 chunks of 32B,
    // this lane covers chunks {sub, sub+4, sub+8, sub+12} of both rows.
    float a[32], b[32];
    ldg256_evict_last(srow + (sub +  0) * 8, a +  0);
    ldg256_evict_last(srow + (sub +  4) * 8, a +  8);
    ldg256_evict_last(srow + (sub +  8) * 8, a + 16);
    ldg256_evict_last(srow + (sub + 12) * 8, a + 24);
    ldg256_evict_last(drow + (sub +  0) * 8, b +  0);
    ldg256_evict_last(drow + (sub +  4) * 8, b +  8);
    ldg256_evict_last(drow + (sub +  8) * 8, b + 16);
    ldg256_evict_last(drow + (sub + 12) * 8, b + 24);

    float sum = 0.0f;
    #pragma unroll
    for (int i = 0; i < 32; i++) sum += a[i] * b[i];

    // Reduce across the 4-lane group
    sum += __shfl_xor_sync(0xFFFFFFFFu, sum, 1);
    sum += __shfl_xor_sync(0xFFFFFFFFu, sum, 2);

    // Streaming store: don't let output churn the L2.
    if (sub == 0) __stcs(&out[e], sum);
}

extern "C" void kernel_launch(void* const* d_in, const int* in_sizes, int n_in,
                              void* d_out, int out_size)
{
    const float* h_user = (const float*)d_in[0];
    const float* h_item = (const float*)d_in[1];
    const int* src_clicks    = (const int*)d_in[2];
    const int* dst_clicks    = (const int*)d_in[3];
    const int* src_clickedby = (const int*)d_in[4];
    const int* dst_clickedby = (const int*)d_in[5];
    const int* src_follows   = (const int*)d_in[6];
    const int* dst_follows   = (const int*)d_in[7];
    float* out = (float*)d_out;

    const int E = in_sizes[2];  // edges per etype (500000)
    const int total = 3 * E;

    const int threads = 256;            // 8 warps x 8 edges = 64 edges/block
    const int blocks = (total + 63) / 64;

    edge_dot128_fused_kernel<<<blocks, threads>>>(
        h_user, h_item,
        src_clicks, dst_clicks,
        src_clickedby, dst_clickedby,
        src_follows, dst_follows,
        out, E);
}